// round 3
// baseline (speedup 1.0000x reference)
#include <cuda_runtime.h>

// ---------------------------------------------------------------------------
// Shapes (fixed by the problem): B=4, N=256, E=64, C=128, H=256.
// out[b,n,m] = W3 . relu(W2 . relu(W1 . concat(edge[b,:,n,m],
//                                              node[b,:,n], node[b,:,m]) + b1) + b2) + b3
//
// Factorization: W1 = [W1e(256x64) | W1r(256x128) | W1c(256x128)]
//   R[b,n,h] = W1r . node[b,:,n]
//   C[b,m,h] = W1c . node[b,:,m] + b1[h]
//   h1[b,n,m,h] = relu(W1e . edge[b,:,n,m] + R[b,n,h] + C[b,m,h])
// ---------------------------------------------------------------------------

__device__ float g_W1eT[64 * 256];     // [e][h]
__device__ float g_W1rT[128 * 256];    // [c][h]
__device__ float g_W1cT[128 * 256];    // [c][h]
__device__ float g_W2T[256 * 256];     // [k][h]
__device__ float g_R[4 * 256 * 256];   // [b][n][h]
__device__ float g_C[4 * 256 * 256];   // [b][m][h]  (b1 folded in)

// --- kernel 1: transpose weights into [k][h] layouts (coalesced consumers) ---
__global__ void prep_transpose(const float* __restrict__ W1,
                               const float* __restrict__ W2) {
    int i = blockIdx.x * 256 + threadIdx.x;   // grid 256 x 256 = 65536
    int k = i >> 8, h = i & 255;
    if (i < 64 * 256)  g_W1eT[i] = W1[h * 320 + k];
    if (i < 128 * 256) {
        g_W1rT[i] = W1[h * 320 + 64 + k];
        g_W1cT[i] = W1[h * 320 + 192 + k];
    }
    g_W2T[i] = W2[h * 256 + k];
}

// --- kernel 2: per-(b,p) node projections R and C ---
__global__ void prep_nodeproj(const float* __restrict__ node,
                              const float* __restrict__ b1) {
    int b = blockIdx.x >> 8, p = blockIdx.x & 255;   // 1024 blocks
    int h = threadIdx.x;                             // 256 threads
    __shared__ float ns[128];
    if (h < 128) ns[h] = node[(b * 128 + h) * 256 + p];
    __syncthreads();
    float r = 0.f, c = 0.f;
#pragma unroll 16
    for (int k = 0; k < 128; k++) {
        float v = ns[k];
        r = fmaf(g_W1rT[k * 256 + h], v, r);
        c = fmaf(g_W1cT[k * 256 + h], v, c);
    }
    int o = (b * 256 + p) * 256 + h;
    g_R[o] = r;
    g_C[o] = c + b1[h];
}

// --- kernel 3: fused per-pixel MLP ---------------------------------------
// Block tile: 64 m-pixels (fixed b, n) x 256 hidden channels.
// 256 threads, thread tile 8x8 (tm = tid&7 covers m, th = tid>>3 covers h).
// Dynamic smem layout (floats):
//   phase 1: Es[64][64] at 0, W1s[64][256] at 4096           (peak 20480)
//   phase 2: h1T[256][64] at 0, W2s[32][256] at 16384,
//            Rs[256] at 24576, red[32][64] reuses W2s region (peak 24832)
#define SMEM_FLOATS (256 * 64 + 32 * 256 + 256)

__global__ __launch_bounds__(256, 2)
void fused_mlp(const float* __restrict__ edge,
               const float* __restrict__ b2,
               const float* __restrict__ W3,
               const float* __restrict__ b3,
               float* __restrict__ out) {
    extern __shared__ float smem[];
    float* Es  = smem;                      // [64][64]
    float* W1s = smem + 64 * 64;            // [64][256]
    float* h1T = smem;                      // [256][64] (reuses Es/W1s)
    float* W2s = smem + 256 * 64;           // [32][256]
    float* Rs  = smem + 256 * 64 + 32 * 256;// [256]
    float* red = smem + 256 * 64;           // [32][64] (reuses W2s at the end)

    const int tid = threadIdx.x;
    const int tm = tid & 7, th = tid >> 3;
    const int mt = blockIdx.x, n = blockIdx.y, b = blockIdx.z;
    const int m0 = mt * 64;

    // load R row for this (b, n)
    if (tid < 64)
        ((float4*)Rs)[tid] = ((const float4*)(g_R + (b * 256 + n) * 256))[tid];

    // load edge tile Es[e][m]   (edge[b, e, n, m0 + m])
    const float* eb = edge + ((b * 64) * 256 + n) * 256 + m0;
#pragma unroll
    for (int r = 0; r < 4; r++) {
        int idx = r * 256 + tid;
        int e = idx >> 4, q = idx & 15;
        ((float4*)Es)[e * 16 + q] = *(const float4*)(eb + e * 65536 + q * 4);
    }
    // load W1e^T [64][256]
#pragma unroll
    for (int r = 0; r < 16; r++)
        ((float4*)W1s)[r * 256 + tid] = ((const float4*)g_W1eT)[r * 256 + tid];
    __syncthreads();

    // ---- phase 1: h1-preact = W1e . edge  (M=64, N=256, K=64) ----
    float acc[8][8];
#pragma unroll
    for (int i = 0; i < 8; i++)
#pragma unroll
        for (int j = 0; j < 8; j++) acc[i][j] = 0.f;

#pragma unroll 8
    for (int k = 0; k < 64; k++) {
        float a[8], w[8];
        *(float4*)(a)     = *(float4*)(Es + k * 64 + tm * 8);
        *(float4*)(a + 4) = *(float4*)(Es + k * 64 + tm * 8 + 4);
        *(float4*)(w)     = *(float4*)(W1s + k * 256 + th * 8);
        *(float4*)(w + 4) = *(float4*)(W1s + k * 256 + th * 8 + 4);
#pragma unroll
        for (int i = 0; i < 8; i++)
#pragma unroll
            for (int j = 0; j < 8; j++)
                acc[i][j] = fmaf(a[i], w[j], acc[i][j]);
    }

    // epilogue 1: relu(acc + R + C), C has b1 folded in
    float rj[8];
#pragma unroll
    for (int j = 0; j < 8; j++) rj[j] = Rs[th * 8 + j];
    const float* Cg = g_C + ((b * 256) + m0) * 256;
#pragma unroll
    for (int i = 0; i < 8; i++) {
        const float* cp = Cg + (tm * 8 + i) * 256 + th * 8;
        float4 c0 = *(const float4*)(cp);
        float4 c1 = *(const float4*)(cp + 4);
        float cv[8] = {c0.x, c0.y, c0.z, c0.w, c1.x, c1.y, c1.z, c1.w};
#pragma unroll
        for (int j = 0; j < 8; j++)
            acc[i][j] = fmaxf(acc[i][j] + rj[j] + cv[j], 0.f);
    }
    __syncthreads();   // done reading Es/W1s; safe to overwrite with h1T

    // store h1 transposed: h1T[h][m]
#pragma unroll
    for (int j = 0; j < 8; j++) {
        float4 p0 = make_float4(acc[0][j], acc[1][j], acc[2][j], acc[3][j]);
        float4 p1 = make_float4(acc[4][j], acc[5][j], acc[6][j], acc[7][j]);
        *(float4*)(h1T + (th * 8 + j) * 64 + tm * 8)     = p0;
        *(float4*)(h1T + (th * 8 + j) * 64 + tm * 8 + 4) = p1;
    }
    __syncthreads();

    // ---- phase 2: h2-preact = W2 . h1  (M=64, N=256, K=256) ----
    float acc2[8][8];
#pragma unroll
    for (int i = 0; i < 8; i++)
#pragma unroll
        for (int j = 0; j < 8; j++) acc2[i][j] = 0.f;

    for (int kc = 0; kc < 256; kc += 32) {
        // stage W2^T chunk [32][256]
        const float4* wsrc = (const float4*)(g_W2T + kc * 256);
#pragma unroll
        for (int r = 0; r < 8; r++)
            ((float4*)W2s)[r * 256 + tid] = wsrc[r * 256 + tid];
        __syncthreads();
#pragma unroll 8
        for (int k = 0; k < 32; k++) {
            float a[8], w[8];
            *(float4*)(a)     = *(float4*)(h1T + (kc + k) * 64 + tm * 8);
            *(float4*)(a + 4) = *(float4*)(h1T + (kc + k) * 64 + tm * 8 + 4);
            *(float4*)(w)     = *(float4*)(W2s + k * 256 + th * 8);
            *(float4*)(w + 4) = *(float4*)(W2s + k * 256 + th * 8 + 4);
#pragma unroll
            for (int i = 0; i < 8; i++)
#pragma unroll
                for (int j = 0; j < 8; j++)
                    acc2[i][j] = fmaf(a[i], w[j], acc2[i][j]);
        }
        __syncthreads();
    }

    // ---- epilogue 2 + layer 3: out[m] = b3 + sum_h W3[h] * relu(acc2 + b2) ----
    float po[8];
#pragma unroll
    for (int i = 0; i < 8; i++) po[i] = 0.f;
#pragma unroll
    for (int j = 0; j < 8; j++) {
        int h = th * 8 + j;
        float w3 = W3[h], bb = b2[h];
#pragma unroll
        for (int i = 0; i < 8; i++)
            po[i] = fmaf(w3, fmaxf(acc2[i][j] + bb, 0.f), po[i]);
    }
    // cross-thread reduction over th (32 groups of 8 h each)
#pragma unroll
    for (int i = 0; i < 8; i++)
        red[th * 64 + tm * 8 + i] = po[i];
    __syncthreads();
    if (tid < 64) {
        float s = b3[0];
#pragma unroll
        for (int t = 0; t < 32; t++) s += red[t * 64 + tid];
        out[(b * 256 + n) * 256 + m0 + tid] = s;
    }
}

extern "C" void kernel_launch(void* const* d_in, const int* in_sizes, int n_in,
                              void* d_out, int out_size) {
    const float* edge = (const float*)d_in[0];
    const float* node = (const float*)d_in[1];
    const float* W1   = (const float*)d_in[2];
    const float* b1   = (const float*)d_in[3];
    const float* W2   = (const float*)d_in[4];
    const float* b2   = (const float*)d_in[5];
    const float* W3   = (const float*)d_in[6];
    const float* b3   = (const float*)d_in[7];
    float* out = (float*)d_out;

    cudaFuncSetAttribute(fused_mlp, cudaFuncAttributeMaxDynamicSharedMemorySize,
                         SMEM_FLOATS * (int)sizeof(float));

    prep_transpose<<<256, 256>>>(W1, W2);
    prep_nodeproj<<<1024, 256>>>(node, b1);
    dim3 grid(4, 256, 4);   // (m-tile, n, b)
    fused_mlp<<<grid, 256, SMEM_FLOATS * sizeof(float)>>>(edge, b2, W3, b3, out);
}

// round 6
// speedup vs baseline: 1.5626x; 1.5626x over previous
#include <cuda_runtime.h>

// ---------------------------------------------------------------------------
// B=4, N=256, E=64, C=128, H=256.
// out[b,n,m] = W3.relu(W2.relu(W1.concat(edge,row,col)+b1)+b2)+b3
// Factorization: R[b,n,h]=W1r.node[:,n] ; C[b,m,h]=W1c.node[:,m]+b1
// Inner GEMMs use packed fma.rn.f32x2 (2 FLOP/issue) — Blackwell f32x2 pipe.
// ---------------------------------------------------------------------------

__device__ float g_W1eT[64 * 256];     // [e][h]
__device__ float g_W1rT[128 * 256];    // [c][h]
__device__ float g_W1cT[128 * 256];    // [c][h]
__device__ float g_W2T[256 * 256];     // [k][h]
__device__ float g_R[4 * 256 * 256];   // [b][n][h]
__device__ float g_C[4 * 256 * 256];   // [b][m][h]  (b1 folded in)

// ---- f32x2 helpers --------------------------------------------------------
__device__ __forceinline__ unsigned long long f2bcast(float v) {
    unsigned long long r;
    asm("mov.b64 %0, {%1, %1};" : "=l"(r) : "f"(v));
    return r;
}
__device__ __forceinline__ void fma2(unsigned long long& d,
                                     unsigned long long a,
                                     unsigned long long b) {
    asm("fma.rn.f32x2 %0, %1, %2, %3;" : "=l"(d) : "l"(a), "l"(b), "l"(d));
}
__device__ __forceinline__ void f2unpack(unsigned long long v, float& lo, float& hi) {
    asm("mov.b64 {%0, %1}, %2;" : "=f"(lo), "=f"(hi) : "l"(v));
}

// --- kernel 1: transpose weights into [k][h] layouts ---
__global__ void prep_transpose(const float* __restrict__ W1,
                               const float* __restrict__ W2) {
    int i = blockIdx.x * 256 + threadIdx.x;   // 65536
    int k = i >> 8, h = i & 255;
    if (i < 64 * 256)  g_W1eT[i] = W1[h * 320 + k];
    if (i < 128 * 256) {
        g_W1rT[i] = W1[h * 320 + 64 + k];
        g_W1cT[i] = W1[h * 320 + 192 + k];
    }
    g_W2T[i] = W2[h * 256 + k];
}

// --- kernel 2: per-(b,p) node projections R and C ---
__global__ void prep_nodeproj(const float* __restrict__ node,
                              const float* __restrict__ b1) {
    int b = blockIdx.x >> 8, p = blockIdx.x & 255;
    int h = threadIdx.x;
    __shared__ float ns[128];
    if (h < 128) ns[h] = node[(b * 128 + h) * 256 + p];
    __syncthreads();
    float r = 0.f, c = 0.f;
#pragma unroll 16
    for (int k = 0; k < 128; k++) {
        float v = ns[k];
        r = fmaf(g_W1rT[k * 256 + h], v, r);
        c = fmaf(g_W1cT[k * 256 + h], v, c);
    }
    int o = (b * 256 + p) * 256 + h;
    g_R[o] = r;
    g_C[o] = c + b1[h];
}

// --- kernel 3: fused per-pixel MLP, f32x2 math ---------------------------
#define SMEM_FLOATS (256 * 64 + 32 * 256 + 256)

__global__ __launch_bounds__(256, 2)
void fused_mlp(const float* __restrict__ edge,
               const float* __restrict__ b2,
               const float* __restrict__ W3,
               const float* __restrict__ b3,
               float* __restrict__ out) {
    extern __shared__ float smem[];
    float* Es  = smem;                       // [64][64]
    float* W1s = smem + 64 * 64;             // [64][256]
    float* h1T = smem;                       // [256][64]
    float* W2s = smem + 256 * 64;            // [32][256]
    float* Rs  = smem + 256 * 64 + 32 * 256; // [256]
    float* red = smem + 256 * 64;            // [32][64]

    const int tid = threadIdx.x;
    const int tm = tid & 7, th = tid >> 3;
    const int mt = blockIdx.x, n = blockIdx.y, b = blockIdx.z;
    const int m0 = mt * 64;

    if (tid < 64)
        ((float4*)Rs)[tid] = ((const float4*)(g_R + (b * 256 + n) * 256))[tid];

    const float* eb = edge + ((b * 64) * 256 + n) * 256 + m0;
#pragma unroll
    for (int r = 0; r < 4; r++) {
        int idx = r * 256 + tid;
        int e = idx >> 4, q = idx & 15;
        ((float4*)Es)[e * 16 + q] = *(const float4*)(eb + e * 65536 + q * 4);
    }
#pragma unroll
    for (int r = 0; r < 16; r++)
        ((float4*)W1s)[r * 256 + tid] = ((const float4*)g_W1eT)[r * 256 + tid];
    __syncthreads();

    // ---- phase 1: h1-preact = W1e . edge  (M=64, N=256, K=64), f32x2 ----
    unsigned long long acc[8][4];
#pragma unroll
    for (int i = 0; i < 8; i++)
#pragma unroll
        for (int j = 0; j < 4; j++) acc[i][j] = 0ULL;

#pragma unroll 4
    for (int k = 0; k < 64; k++) {
        float a[8];
        *(float4*)(a)     = *(float4*)(Es + k * 64 + tm * 8);
        *(float4*)(a + 4) = *(float4*)(Es + k * 64 + tm * 8 + 4);
        ulonglong2 w01 = *(ulonglong2*)(W1s + k * 256 + th * 8);
        ulonglong2 w23 = *(ulonglong2*)(W1s + k * 256 + th * 8 + 4);
#pragma unroll
        for (int i = 0; i < 8; i++) {
            unsigned long long ap = f2bcast(a[i]);
            fma2(acc[i][0], ap, w01.x);
            fma2(acc[i][1], ap, w01.y);
            fma2(acc[i][2], ap, w23.x);
            fma2(acc[i][3], ap, w23.y);
        }
    }

    // epilogue 1: relu(acc + R + C)
    float accf[8][8];
#pragma unroll
    for (int i = 0; i < 8; i++)
#pragma unroll
        for (int j = 0; j < 4; j++)
            f2unpack(acc[i][j], accf[i][2 * j], accf[i][2 * j + 1]);

    float rj[8];
#pragma unroll
    for (int j = 0; j < 8; j++) rj[j] = Rs[th * 8 + j];
    const float* Cg = g_C + ((b * 256) + m0) * 256;
#pragma unroll
    for (int i = 0; i < 8; i++) {
        const float* cp = Cg + (tm * 8 + i) * 256 + th * 8;
        float4 c0 = *(const float4*)(cp);
        float4 c1 = *(const float4*)(cp + 4);
        float cv[8] = {c0.x, c0.y, c0.z, c0.w, c1.x, c1.y, c1.z, c1.w};
#pragma unroll
        for (int j = 0; j < 8; j++)
            accf[i][j] = fmaxf(accf[i][j] + rj[j] + cv[j], 0.f);
    }
    __syncthreads();

    // store h1 transposed: h1T[h][m]
#pragma unroll
    for (int j = 0; j < 8; j++) {
        float4 p0 = make_float4(accf[0][j], accf[1][j], accf[2][j], accf[3][j]);
        float4 p1 = make_float4(accf[4][j], accf[5][j], accf[6][j], accf[7][j]);
        *(float4*)(h1T + (th * 8 + j) * 64 + tm * 8)     = p0;
        *(float4*)(h1T + (th * 8 + j) * 64 + tm * 8 + 4) = p1;
    }
    __syncthreads();

    // ---- phase 2: h2-preact = W2 . h1  (M=64, N=256, K=256), f32x2 ----
    unsigned long long acc2[8][4];
#pragma unroll
    for (int i = 0; i < 8; i++)
#pragma unroll
        for (int j = 0; j < 4; j++) acc2[i][j] = 0ULL;

    for (int kc = 0; kc < 256; kc += 32) {
        const float4* wsrc = (const float4*)(g_W2T + kc * 256);
#pragma unroll
        for (int r = 0; r < 8; r++)
            ((float4*)W2s)[r * 256 + tid] = wsrc[r * 256 + tid];
        __syncthreads();
#pragma unroll 4
        for (int k = 0; k < 32; k++) {
            float a[8];
            *(float4*)(a)     = *(float4*)(h1T + (kc + k) * 64 + tm * 8);
            *(float4*)(a + 4) = *(float4*)(h1T + (kc + k) * 64 + tm * 8 + 4);
            ulonglong2 w01 = *(ulonglong2*)(W2s + k * 256 + th * 8);
            ulonglong2 w23 = *(ulonglong2*)(W2s + k * 256 + th * 8 + 4);
#pragma unroll
            for (int i = 0; i < 8; i++) {
                unsigned long long ap = f2bcast(a[i]);
                fma2(acc2[i][0], ap, w01.x);
                fma2(acc2[i][1], ap, w01.y);
                fma2(acc2[i][2], ap, w23.x);
                fma2(acc2[i][3], ap, w23.y);
            }
        }
        __syncthreads();
    }

    // ---- epilogue 2 + layer 3 ----
    float po[8];
#pragma unroll
    for (int i = 0; i < 8; i++) po[i] = 0.f;
#pragma unroll
    for (int j2 = 0; j2 < 4; j2++) {
        int h0 = th * 8 + 2 * j2;
        float w3a = W3[h0],     bba = b2[h0];
        float w3b = W3[h0 + 1], bbb = b2[h0 + 1];
#pragma unroll
        for (int i = 0; i < 8; i++) {
            float lo, hi;
            f2unpack(acc2[i][j2], lo, hi);
            po[i] = fmaf(w3a, fmaxf(lo + bba, 0.f), po[i]);
            po[i] = fmaf(w3b, fmaxf(hi + bbb, 0.f), po[i]);
        }
    }
#pragma unroll
    for (int i = 0; i < 8; i++)
        red[th * 64 + tm * 8 + i] = po[i];
    __syncthreads();
    if (tid < 64) {
        float s = b3[0];
#pragma unroll
        for (int t = 0; t < 32; t++) s += red[t * 64 + tid];
        out[(b * 256 + n) * 256 + m0 + tid] = s;
    }
}

extern "C" void kernel_launch(void* const* d_in, const int* in_sizes, int n_in,
                              void* d_out, int out_size) {
    const float* edge = (const float*)d_in[0];
    const float* node = (const float*)d_in[1];
    const float* W1   = (const float*)d_in[2];
    const float* b1   = (const float*)d_in[3];
    const float* W2   = (const float*)d_in[4];
    const float* b2   = (const float*)d_in[5];
    const float* W3   = (const float*)d_in[6];
    const float* b3   = (const float*)d_in[7];
    float* out = (float*)d_out;

    cudaFuncSetAttribute(fused_mlp, cudaFuncAttributeMaxDynamicSharedMemorySize,
                         SMEM_FLOATS * (int)sizeof(float));

    prep_transpose<<<256, 256>>>(W1, W2);
    prep_nodeproj<<<1024, 256>>>(node, b1);
    dim3 grid(4, 256, 4);   // (m-tile, n, b)
    fused_mlp<<<grid, 256, SMEM_FLOATS * sizeof(float)>>>(edge, b2, W3, b3, out);
}

// round 7
// speedup vs baseline: 2.0331x; 1.3011x over previous
#include <cuda_runtime.h>
#include <cuda_bf16.h>

// ---------------------------------------------------------------------------
// B=4, N=256, E=64, C=128, H=256.
// out[b,n,m] = W3.relu(W2.relu(W1.concat(edge,row,col)+b1)+b2)+b3
// R[b,n,h] = W1r.node[:,n] + b1 ; C[b,m,h] = W1c.node[:,m]
// Both GEMMs on tensor cores via legacy mma.sync m16n8k16 bf16 (sm_80 PTX,
// compiles under compute_103) with 3-pass hi/lo split for fp32-like accuracy.
// ---------------------------------------------------------------------------

__device__ float g_W1rT[128 * 256];
__device__ float g_W1cT[128 * 256];
__device__ float g_R[4 * 256 * 256];          // + b1 folded
__device__ float g_C[4 * 256 * 256];
__device__ __nv_bfloat16 g_W1hi[256 * 64];    // [h][k] row-major
__device__ __nv_bfloat16 g_W1lo[256 * 64];
__device__ __nv_bfloat16 g_W2hi[256 * 256];   // [h_out][h_in] row-major
__device__ __nv_bfloat16 g_W2lo[256 * 256];

// ---------------- helpers --------------------------------------------------
__device__ __forceinline__ void ldsm4(unsigned a[4], unsigned addr) {
    asm volatile("ldmatrix.sync.aligned.m8n8.x4.shared.b16 {%0,%1,%2,%3}, [%4];"
                 : "=r"(a[0]), "=r"(a[1]), "=r"(a[2]), "=r"(a[3]) : "r"(addr));
}
__device__ __forceinline__ void ldsm2(unsigned b[2], unsigned addr) {
    asm volatile("ldmatrix.sync.aligned.m8n8.x2.shared.b16 {%0,%1}, [%2];"
                 : "=r"(b[0]), "=r"(b[1]) : "r"(addr));
}
__device__ __forceinline__ void mma16816(float d[4], const unsigned a[4],
                                         unsigned b0, unsigned b1) {
    asm volatile(
        "mma.sync.aligned.m16n8k16.row.col.f32.bf16.bf16.f32 "
        "{%0,%1,%2,%3}, {%4,%5,%6,%7}, {%8,%9}, {%0,%1,%2,%3};"
        : "+f"(d[0]), "+f"(d[1]), "+f"(d[2]), "+f"(d[3])
        : "r"(a[0]), "r"(a[1]), "r"(a[2]), "r"(a[3]), "r"(b0), "r"(b1));
}
__device__ __forceinline__ void split2(float v0, float v1,
                                       unsigned& hiw, unsigned& low) {
    __nv_bfloat16 h0 = __float2bfloat16(v0);
    __nv_bfloat16 h1 = __float2bfloat16(v1);
    __nv_bfloat16 l0 = __float2bfloat16(v0 - __bfloat162float(h0));
    __nv_bfloat16 l1 = __float2bfloat16(v1 - __bfloat162float(h1));
    hiw = (unsigned)__bfloat16_as_ushort(h0) |
          ((unsigned)__bfloat16_as_ushort(h1) << 16);
    low = (unsigned)__bfloat16_as_ushort(l0) |
          ((unsigned)__bfloat16_as_ushort(l1) << 16);
}

// ---------------- prep kernels ---------------------------------------------
__global__ void prep_tr(const float* __restrict__ W1) {
    int i = blockIdx.x * 256 + threadIdx.x;   // 32768
    int c = i >> 8, h = i & 255;
    g_W1rT[i] = W1[h * 320 + 64 + c];
    g_W1cT[i] = W1[h * 320 + 192 + c];
}

__global__ void prep_np(const float* __restrict__ node, const float* __restrict__ b1) {
    int b = blockIdx.x >> 8, p = blockIdx.x & 255;
    int h = threadIdx.x;
    __shared__ float ns[128];
    if (h < 128) ns[h] = node[(b * 128 + h) * 256 + p];
    __syncthreads();
    float r = 0.f, c = 0.f;
#pragma unroll 16
    for (int k = 0; k < 128; k++) {
        float v = ns[k];
        r = fmaf(g_W1rT[k * 256 + h], v, r);
        c = fmaf(g_W1cT[k * 256 + h], v, c);
    }
    int o = (b * 256 + p) * 256 + h;
    g_R[o] = r + b1[h];
    g_C[o] = c;
}

__global__ void prep_w1(const float* __restrict__ W1) {
    int i = blockIdx.x * 256 + threadIdx.x;   // 16384
    int h = i >> 6, k = i & 63;
    float v = W1[h * 320 + k];
    __nv_bfloat16 hi = __float2bfloat16(v);
    g_W1hi[i] = hi;
    g_W1lo[i] = __float2bfloat16(v - __bfloat162float(hi));
}

__global__ void prep_w2(const float* __restrict__ W2) {
    int i = blockIdx.x * 256 + threadIdx.x;   // 65536
    float v = W2[i];
    __nv_bfloat16 hi = __float2bfloat16(v);
    g_W2hi[i] = hi;
    g_W2lo[i] = __float2bfloat16(v - __bfloat162float(hi));
}

__global__ void zero_out(float* __restrict__ out, const float* __restrict__ b3) {
    out[blockIdx.x * 256 + threadIdx.x] = b3[0];
}

// ---------------- main tensor-core kernel ----------------------------------
// SMEM layout (bytes):
#define SW2HI 0         // 128 x 512  W2 half hi (swizzled)
#define SW2LO 65536     // 128 x 512  W2 half lo
#define SA1HI 131072    // 32 x 128   edge tile hi (swizzled)
#define SA1LO 135168
#define SH1HI 139264    // 32 x 512   h1 hi (swizzled)
#define SH1LO 155648
#define SRS   172032    // 256 f32  R row
#define SW3O  173056    // 128 f32
#define SB2O  173568    // 128 f32
#define SMEM_TOTAL 174080

__global__ __launch_bounds__(256, 1)
void mlp_mma(const float* __restrict__ edge, const float* __restrict__ b2,
             const float* __restrict__ W3, float* __restrict__ out) {
    extern __shared__ char smem[];
    const int tid = threadIdx.x;
    const int wid = tid >> 5, lane = tid & 31;
    const int g = lane >> 2, t4 = lane & 3;
    const int hh = blockIdx.x & 1;

    // stage W2 half into SMEM with XOR-16B swizzle; W3/b2 halves
    {
        const uint4* s2h = (const uint4*)g_W2hi + (size_t)(hh * 128) * 32;
        const uint4* s2l = (const uint4*)g_W2lo + (size_t)(hh * 128) * 32;
        uint4* d2h = (uint4*)(smem + SW2HI);
        uint4* d2l = (uint4*)(smem + SW2LO);
        for (int i = tid; i < 4096; i += 256) {
            int r = i >> 5, c = i & 31;
            int dc = c ^ (r & 7);
            d2h[r * 32 + dc] = s2h[i];
            d2l[r * 32 + dc] = s2l[i];
        }
        if (tid < 128) {
            ((float*)(smem + SW3O))[tid] = W3[hh * 128 + tid];
            ((float*)(smem + SB2O))[tid] = b2[hh * 128 + tid];
        }
    }
    const unsigned sb = (unsigned)__cvta_generic_to_shared(smem);
    const unsigned* w1hi = (const unsigned*)g_W1hi;
    const unsigned* w1lo = (const unsigned*)g_W1lo;
    const float* RS  = (const float*)(smem + SRS);
    const float* w3s = (const float*)(smem + SW3O);
    const float* b2s = (const float*)(smem + SB2O);

    const int hb1 = wid * 32;   // GEMM1: this warp's 32 output h (of 256)
    const int hb2 = wid * 16;   // GEMM2: this warp's 16 h' (of 128 half)

    for (int t = blockIdx.x >> 1; t < 8192; t += 74) {
        const int mt = t & 7, n = (t >> 3) & 255, b = t >> 11;
        const int m0 = mt * 32;

        // ---- load: edge tile -> A1 hi/lo (swizzled), R row ----
        {
            const int px = tid & 31, e0 = tid >> 5;
            const float* ep =
                edge + ((size_t)(b * 64 + e0 * 8) * 256 + n) * 256 + m0 + px;
            float v[8];
#pragma unroll
            for (int j = 0; j < 8; j++) v[j] = ep[(size_t)j * 65536];
            unsigned rowoff = px * 128 + ((e0 ^ (px & 7)) * 16);
#pragma unroll
            for (int p = 0; p < 4; p++) {
                unsigned hiw, low;
                split2(v[2 * p], v[2 * p + 1], hiw, low);
                *(unsigned*)(smem + SA1HI + rowoff + p * 4) = hiw;
                *(unsigned*)(smem + SA1LO + rowoff + p * 4) = low;
            }
            ((float*)(smem + SRS))[tid] = g_R[((b * 256 + n) << 8) + tid];
        }
        __syncthreads();

        // ---- GEMM1: D1[32px, 256h] = A1 x W1e^T, K=64, 3 split passes ----
        float acc1[2][4][4];
#pragma unroll
        for (int mi = 0; mi < 2; mi++)
#pragma unroll
            for (int ni = 0; ni < 4; ni++)
#pragma unroll
                for (int q = 0; q < 4; q++) acc1[mi][ni][q] = 0.f;

#pragma unroll
        for (int kc = 0; kc < 4; kc++) {
            unsigned ah[2][4], al[2][4];
#pragma unroll
            for (int mi = 0; mi < 2; mi++) {
                int px = mi * 16 + (lane & 15);
                unsigned ch = (unsigned)(kc * 2 + (lane >> 4)) ^ (px & 7);
                unsigned ad = sb + SA1HI + px * 128 + ch * 16;
                ldsm4(ah[mi], ad);
                ldsm4(al[mi], ad + (SA1LO - SA1HI));
            }
            unsigned bh0[4], bh1[4], bl0[4], bl1[4];
#pragma unroll
            for (int ni = 0; ni < 4; ni++) {
                int idx = (hb1 + ni * 8 + g) * 32 + kc * 8 + t4;
                bh0[ni] = w1hi[idx];  bh1[ni] = w1hi[idx + 4];
                bl0[ni] = w1lo[idx];  bl1[ni] = w1lo[idx + 4];
            }
#pragma unroll
            for (int ni = 0; ni < 4; ni++)
#pragma unroll
                for (int mi = 0; mi < 2; mi++) {
                    mma16816(acc1[mi][ni], ah[mi], bh0[ni], bh1[ni]);
                    mma16816(acc1[mi][ni], al[mi], bh0[ni], bh1[ni]);
                    mma16816(acc1[mi][ni], ah[mi], bl0[ni], bl1[ni]);
                }
        }

        // ---- epilogue 1: relu(D1 + R + C) -> h1 hi/lo in SMEM ----
        {
            const float* Cbase = g_C + ((size_t)(b * 256 + m0) << 8);
#pragma unroll
            for (int mi = 0; mi < 2; mi++)
#pragma unroll
                for (int ni = 0; ni < 4; ni++) {
                    int h = hb1 + ni * 8 + 2 * t4;
                    int px0 = mi * 16 + g, px1 = px0 + 8;
                    float r0 = RS[h], r1 = RS[h + 1];
                    float2 C0 = *(const float2*)(Cbase + (px0 << 8) + h);
                    float2 C1 = *(const float2*)(Cbase + (px1 << 8) + h);
                    float v00 = fmaxf(acc1[mi][ni][0] + r0 + C0.x, 0.f);
                    float v01 = fmaxf(acc1[mi][ni][1] + r1 + C0.y, 0.f);
                    float v10 = fmaxf(acc1[mi][ni][2] + r0 + C1.x, 0.f);
                    float v11 = fmaxf(acc1[mi][ni][3] + r1 + C1.y, 0.f);
                    int w = h >> 1, cch = w >> 2, p = w & 3;
                    unsigned hiw, low;
                    split2(v00, v01, hiw, low);
                    unsigned o0 = px0 * 512 + (((unsigned)cch ^ (px0 & 7)) * 16) + p * 4;
                    *(unsigned*)(smem + SH1HI + o0) = hiw;
                    *(unsigned*)(smem + SH1LO + o0) = low;
                    split2(v10, v11, hiw, low);
                    unsigned o1 = px1 * 512 + (((unsigned)cch ^ (px1 & 7)) * 16) + p * 4;
                    *(unsigned*)(smem + SH1HI + o1) = hiw;
                    *(unsigned*)(smem + SH1LO + o1) = low;
                }
        }
        __syncthreads();

        // ---- GEMM2: D2[32px, 16h'] = h1 x W2half^T, K=256, 3 passes ----
        float acc2[2][2][4];
#pragma unroll
        for (int mi = 0; mi < 2; mi++)
#pragma unroll
            for (int ni = 0; ni < 2; ni++)
#pragma unroll
                for (int q = 0; q < 4; q++) acc2[mi][ni][q] = 0.f;

#pragma unroll 4
        for (int kc = 0; kc < 16; kc++) {
            unsigned ah[2][4], al[2][4];
#pragma unroll
            for (int mi = 0; mi < 2; mi++) {
                int px = mi * 16 + (lane & 15);
                unsigned ch = (unsigned)(kc * 2 + (lane >> 4)) ^ (px & 7);
                unsigned ad = sb + SH1HI + px * 512 + ch * 16;
                ldsm4(ah[mi], ad);
                ldsm4(al[mi], ad + (SH1LO - SH1HI));
            }
            unsigned bh[2][2], bl[2][2];
#pragma unroll
            for (int ni = 0; ni < 2; ni++) {
                int hr = hb2 + ni * 8 + (lane & 7);
                unsigned ch = (unsigned)(kc * 2 + ((lane >> 3) & 1)) ^ (hr & 7);
                unsigned bd = sb + SW2HI + hr * 512 + ch * 16;
                ldsm2(bh[ni], bd);
                ldsm2(bl[ni], bd + (SW2LO - SW2HI));
            }
#pragma unroll
            for (int ni = 0; ni < 2; ni++)
#pragma unroll
                for (int mi = 0; mi < 2; mi++) {
                    mma16816(acc2[mi][ni], ah[mi], bh[ni][0], bh[ni][1]);
                    mma16816(acc2[mi][ni], al[mi], bh[ni][0], bh[ni][1]);
                    mma16816(acc2[mi][ni], ah[mi], bl[ni][0], bl[ni][1]);
                }
        }

        // ---- epilogue 2 + layer 3 + atomic combine ----
        {
            float po[2][2] = {{0.f, 0.f}, {0.f, 0.f}};
#pragma unroll
            for (int mi = 0; mi < 2; mi++)
#pragma unroll
                for (int ni = 0; ni < 2; ni++) {
                    int h = hb2 + ni * 8 + 2 * t4;
                    float w3a = w3s[h], w3b = w3s[h + 1];
                    float ba = b2s[h], bb = b2s[h + 1];
                    po[mi][0] = fmaf(w3a, fmaxf(acc2[mi][ni][0] + ba, 0.f), po[mi][0]);
                    po[mi][0] = fmaf(w3b, fmaxf(acc2[mi][ni][1] + bb, 0.f), po[mi][0]);
                    po[mi][1] = fmaf(w3a, fmaxf(acc2[mi][ni][2] + ba, 0.f), po[mi][1]);
                    po[mi][1] = fmaf(w3b, fmaxf(acc2[mi][ni][3] + bb, 0.f), po[mi][1]);
                }
#pragma unroll
            for (int mi = 0; mi < 2; mi++)
#pragma unroll
                for (int r = 0; r < 2; r++) {
                    po[mi][r] += __shfl_xor_sync(0xffffffffu, po[mi][r], 1);
                    po[mi][r] += __shfl_xor_sync(0xffffffffu, po[mi][r], 2);
                }
            if (t4 == 0) {
                int ob = ((b * 256 + n) << 8) + m0;
#pragma unroll
                for (int mi = 0; mi < 2; mi++) {
                    atomicAdd(out + ob + mi * 16 + g, po[mi][0]);
                    atomicAdd(out + ob + mi * 16 + g + 8, po[mi][1]);
                }
            }
        }
        // no sync needed here: next-iter SMEM writes are fenced by the
        // post-load __syncthreads (all warps are past all SMEM reads of
        // A1/RS by then, and SH1 is only rewritten after that barrier).
    }
}

extern "C" void kernel_launch(void* const* d_in, const int* in_sizes, int n_in,
                              void* d_out, int out_size) {
    const float* edge = (const float*)d_in[0];
    const float* node = (const float*)d_in[1];
    const float* W1   = (const float*)d_in[2];
    const float* b1   = (const float*)d_in[3];
    const float* W2   = (const float*)d_in[4];
    const float* b2   = (const float*)d_in[5];
    const float* W3   = (const float*)d_in[6];
    const float* b3   = (const float*)d_in[7];
    float* out = (float*)d_out;

    cudaFuncSetAttribute(mlp_mma, cudaFuncAttributeMaxDynamicSharedMemorySize,
                         SMEM_TOTAL);

    prep_tr<<<128, 256>>>(W1);
    prep_np<<<1024, 256>>>(node, b1);
    prep_w1<<<64, 256>>>(W1);
    prep_w2<<<256, 256>>>(W2);
    zero_out<<<1024, 256>>>(out, b3);
    mlp_mma<<<148, 256, SMEM_TOTAL>>>(edge, b2, W3, out);
}